// round 15
// baseline (speedup 1.0000x reference)
#include <cuda_runtime.h>
#include <math.h>

#define EPS 1e-5f
typedef unsigned long long u64;

// ---------------- scratch (allocation forbidden -> __device__ globals) ----
__device__ float g_x1[4u * 64u * 128u * 128u];     // gelu(conv1(x))   16.8 MB
__device__ float g_r[4u * 16u * 128u * 128u];      // relu(bn(reduce))  4.2 MB

// ---------------- f32x2 helpers ----------------
__device__ __forceinline__ u64 pack2(float a, float b) {
    u64 r; asm("mov.b64 %0,{%1,%2};" : "=l"(r) : "f"(a), "f"(b)); return r;
}
__device__ __forceinline__ void unpack2(u64 v, float &a, float &b) {
    asm("mov.b64 {%0,%1},%2;" : "=f"(a), "=f"(b) : "l"(v));
}
__device__ __forceinline__ u64 fma2(u64 a, u64 b, u64 c) {
    u64 d; asm("fma.rn.f32x2 %0,%1,%2,%3;" : "=l"(d) : "l"(a), "l"(b), "l"(c)); return d;
}

// ---------------- fast exact-erf GELU (A&S 7.1.26, |erf err| < 1.5e-7) ----
__device__ __forceinline__ float gelu1(float v) {
    float ax = fabsf(v) * 0.70710678118654752440f;
    float d  = fmaf(0.3275911f, ax, 1.0f);
    float t; asm("rcp.approx.f32 %0,%1;" : "=f"(t) : "f"(d));
    float p = fmaf(1.061405429f, t, -1.453152027f);
    p = fmaf(p, t, 1.421413741f);
    p = fmaf(p, t, -0.284496736f);
    p = fmaf(p, t, 0.254829592f);
    p = p * t;
    float e = __expf(-ax * ax);
    float er = fmaf(-p, e, 1.0f);
    er = copysignf(er, v);
    return 0.5f * v * (1.0f + er);
}

// ===========================================================================
// Kernel 1 (R15): TWO THREADS per pixel (h = channel half), 256 thr/CTA.
//   x1 = gelu(w1@x); r = relu(bn(wr@x1)) via smem partial.
// Mapping skip REMOVED (now computed in k_main epilogue from x).
// ===========================================================================
#define KP_W1N 0        // 2048  [ci][o]
#define KP_WRN 2048     // 1024  [c][j]
#define KP_SRV 3072     // 16
#define KP_TRV 3088     // 16
#define KP_RP  3104     // 2176  r-partial buffer [128 px][17]
#define KP_FLOATS 5280
#define KP_BYTES (KP_FLOATS * 4)

extern __shared__ __align__(16) float smem[];

__global__ void __launch_bounds__(256, 3) k_pre(
    const float* __restrict__ x,  const float* __restrict__ w1,
    const float* __restrict__ wr, const float* __restrict__ gr,
    const float* __restrict__ br, const float* __restrict__ mr,
    const float* __restrict__ vr)
{
    float* w1n = smem + KP_W1N;
    float* wrn = smem + KP_WRN;
    float* srv = smem + KP_SRV;
    float* trv = smem + KP_TRV;
    float* rbuf = smem + KP_RP;

    const int tid = threadIdx.x;
    for (int i = tid; i < 2048; i += 256) {
        int ci = i >> 6, o = i & 63;
        w1n[ci * 64 + o] = w1[o * 32 + ci];
    }
    for (int i = tid; i < 1024; i += 256) {
        int c = i >> 4, j = i & 15;
        wrn[c * 16 + j] = wr[j * 64 + c];
    }
    if (tid < 16) {
        float s = gr[tid] * rsqrtf(vr[tid] + EPS);
        srv[tid] = s; trv[tid] = br[tid] - mr[tid] * s;
    }
    __syncthreads();

    const int p = tid & 127, h = tid >> 7;           // pixel-in-CTA, channel half
    const int pg = blockIdx.x * 128 + p;             // global pixel id
    const int b = pg >> 14, pix = pg & 16383;
    const float* xb = x + ((size_t)b << 19) + pix;

    float xv[32];
#pragma unroll
    for (int ci = 0; ci < 32; ci++) xv[ci] = __ldg(xb + ((size_t)ci << 14));

    // ---- conv1 (this thread's 32 outs, in 2 sub-blocks of 16) + gelu
    //      + r-partial over own 32 x1 channels ----
    u64 rp[8];
#pragma unroll
    for (int q = 0; q < 8; q++) rp[q] = 0ull;
    float* x1o = g_x1 + ((size_t)b << 20) + pix;
#pragma unroll
    for (int sub = 0; sub < 2; sub++) {
        const int base = h * 32 + sub * 16;          // first out channel
        u64 acc[8];
#pragma unroll
        for (int q = 0; q < 8; q++) acc[q] = 0ull;
#pragma unroll 4
        for (int ci = 0; ci < 32; ci++) {
            u64 xd = pack2(xv[ci], xv[ci]);
            const ulonglong2* wp = (const ulonglong2*)(w1n + ci * 64 + base);
#pragma unroll
            for (int q = 0; q < 4; q++) {
                ulonglong2 w = wp[q];
                acc[2 * q]     = fma2(w.x, xd, acc[2 * q]);
                acc[2 * q + 1] = fma2(w.y, xd, acc[2 * q + 1]);
            }
        }
#pragma unroll
        for (int lc = 0; lc < 8; lc++) {
            int c0 = base + 2 * lc;
            float v0, v1; unpack2(acc[lc], v0, v1);
            float g0 = gelu1(v0), g1 = gelu1(v1);
            x1o[(size_t)c0 << 14]       = g0;
            x1o[(size_t)(c0 + 1) << 14] = g1;
            u64 g0d = pack2(g0, g0), g1d = pack2(g1, g1);
            const ulonglong2* r0 = (const ulonglong2*)(wrn + c0 * 16);
            const ulonglong2* r1 = (const ulonglong2*)(wrn + (c0 + 1) * 16);
#pragma unroll
            for (int q = 0; q < 4; q++) {
                ulonglong2 wA = r0[q];
                rp[2 * q]     = fma2(wA.x, g0d, rp[2 * q]);
                rp[2 * q + 1] = fma2(wA.y, g0d, rp[2 * q + 1]);
                ulonglong2 wB = r1[q];
                rp[2 * q]     = fma2(wB.x, g1d, rp[2 * q]);
                rp[2 * q + 1] = fma2(wB.y, g1d, rp[2 * q + 1]);
            }
        }
    }
    // ---- combine r partials: h=1 stores, h=0 adds + bn + relu -> g_r ----
    if (h == 1) {
#pragma unroll
        for (int q = 0; q < 8; q++) {
            float a0, a1; unpack2(rp[q], a0, a1);
            rbuf[p * 17 + 2 * q]     = a0;
            rbuf[p * 17 + 2 * q + 1] = a1;
        }
    }
    __syncthreads();
    if (h == 0) {
        float* ro = g_r + (((size_t)b * 16) << 14) + pix;
#pragma unroll
        for (int q = 0; q < 8; q++) {
            float a0, a1; unpack2(rp[q], a0, a1);
            a0 += rbuf[p * 17 + 2 * q];
            a1 += rbuf[p * 17 + 2 * q + 1];
            ro[(size_t)(2 * q) << 14]     = fmaxf(fmaf(srv[2 * q],     a0, trv[2 * q]),     0.f);
            ro[(size_t)(2 * q + 1) << 14] = fmaxf(fmaf(srv[2 * q + 1], a1, trv[2 * q + 1]), 0.f);
        }
    }
}

// ===========================================================================
// Kernel 2 (R15): span-weight JIT + involution + BN1 + GELU + conv2(BN2
// folded) + GELU, with the mapping skip computed IN the epilogue from x
// (g_skip buffer eliminated). Tile 16x8, 512 threads, 2 CTAs/SM.
// ===========================================================================
#define TW 16
#define TH 8
#define HW 22
#define HP 308
#define CSTR 68
#define KM_X1S 0
#define KM_W2T (HP * CSTR)
#define KM_WSS (KM_W2T + 4096)
#define KM_S1V (KM_WSS + 3584)
#define KM_T1V (KM_S1V + 64)
#define KM_T2V (KM_T1V + 64)
#define KM_FLOATS (KM_T2V + 64)
#define KM_BYTES (KM_FLOATS * 4)

__global__ void __launch_bounds__(512, 2) k_main(
    const float* __restrict__ x,  const float* __restrict__ wm,
    const float* __restrict__ bmap, const float* __restrict__ gm,
    const float* __restrict__ betam, const float* __restrict__ mm,
    const float* __restrict__ vm,
    const float* __restrict__ ws, const float* __restrict__ bs,
    const float* __restrict__ g1, const float* __restrict__ b1,
    const float* __restrict__ m1, const float* __restrict__ v1,
    const float* __restrict__ w2, const float* __restrict__ g2,
    const float* __restrict__ b2, const float* __restrict__ m2,
    const float* __restrict__ v2, float* __restrict__ out)
{
    float* x1s = smem + KM_X1S;
    float* w2t = smem + KM_W2T;
    float* wss = smem + KM_WSS;
    float* s1v = smem + KM_S1V;
    float* t1v = smem + KM_T1V;
    float* t2v = smem + KM_T2V;

    const int tid = threadIdx.x;
    const int b = blockIdx.z;
    const int tx0 = blockIdx.x * TW, ty0 = blockIdx.y * TH;

    for (int i = tid; i < 4096; i += 512) {
        int c = i >> 6, o = i & 63;
        float s2 = g2[o] * rsqrtf(v2[o] + EPS);
        w2t[c * 64 + o] = w2[o * 64 + c] * s2;
    }
    for (int i = tid; i < 3584; i += 512) {
        int dj = i & 7, j = (i >> 3) & 15, gd = i >> 7;
        int di = gd % 7, gq = gd / 7;
        wss[i] = (dj < 7) ? ws[(gq * 49 + di * 7 + dj) * 16 + j] : 0.f;
    }
    if (tid < 64) {
        float s1 = g1[tid] * rsqrtf(v1[tid] + EPS);
        s1v[tid] = s1; t1v[tid] = b1[tid] - m1[tid] * s1;
        float s2 = g2[tid] * rsqrtf(v2[tid] + EPS);
        t2v[tid] = b2[tid] - m2[tid] * s2;
    }

    const float* x1b = g_x1 + ((size_t)b << 20);
    for (int i = tid; i < HP * 64; i += 512) {
        int c = i / HP, hp = i - c * HP;
        int hy = hp / HW, hx = hp - hy * HW;
        int gy = ty0 - 3 + hy, gx = tx0 - 3 + hx;
        float v = 0.f;
        if (gy >= 0 && gy < 128 && gx >= 0 && gx < 128)
            v = __ldg(x1b + ((size_t)c << 14) + (gy << 7) + gx);
        x1s[hp * CSTR + c] = v;
    }
    __syncthreads();

    const int p = tid & 127, g = tid >> 7;
    const int py = p >> 4, px = p & 15;
    const int gy = ty0 + py, gx = tx0 + px;
    const int pix = (gy << 7) + gx;
    const int ch0 = g * 16;

    float r16[16];
    const float* rb = g_r + (((size_t)b * 16) << 14) + pix;
#pragma unroll
    for (int j = 0; j < 16; j++) r16[j] = __ldg(rb + ((size_t)j << 14));

    u64 acc[8];
#pragma unroll
    for (int q = 0; q < 8; q++) acc[q] = 0ull;
#pragma unroll
    for (int di = 0; di < 7; di++) {
        const float* bsp = bs + g * 49 + di * 7;
        u64 wa[4];
        wa[0] = pack2(__ldg(bsp + 0), __ldg(bsp + 1));
        wa[1] = pack2(__ldg(bsp + 2), __ldg(bsp + 3));
        wa[2] = pack2(__ldg(bsp + 4), __ldg(bsp + 5));
        wa[3] = pack2(__ldg(bsp + 6), 0.f);
        const ulonglong2* wsp = (const ulonglong2*)(wss + ((g * 7 + di) * 16) * 8);
#pragma unroll
        for (int j = 0; j < 16; j++) {
            u64 rd = pack2(r16[j], r16[j]);
            ulonglong2 wA = wsp[2 * j];
            ulonglong2 wB = wsp[2 * j + 1];
            wa[0] = fma2(wA.x, rd, wa[0]);
            wa[1] = fma2(wA.y, rd, wa[1]);
            wa[2] = fma2(wB.x, rd, wa[2]);
            wa[3] = fma2(wB.y, rd, wa[3]);
        }
        float w7[8];
        unpack2(wa[0], w7[0], w7[1]); unpack2(wa[1], w7[2], w7[3]);
        unpack2(wa[2], w7[4], w7[5]); unpack2(wa[3], w7[6], w7[7]);

        const float* rowb = x1s + ((py + di) * HW + px) * CSTR + ch0;
#pragma unroll
        for (int dj = 0; dj < 7; dj++) {
            u64 kp = pack2(w7[dj], w7[dj]);
            const ulonglong2* xp = (const ulonglong2*)(rowb + dj * CSTR);
#pragma unroll
            for (int q = 0; q < 4; q++) {
                ulonglong2 xv = xp[q];
                acc[2 * q]     = fma2(kp, xv.x, acc[2 * q]);
                acc[2 * q + 1] = fma2(kp, xv.y, acc[2 * q + 1]);
            }
        }
    }
    float y[16];
#pragma unroll
    for (int q = 0; q < 8; q++) {
        u64 s = *(const u64*)(s1v + ch0 + 2 * q);
        u64 t = *(const u64*)(t1v + ch0 + 2 * q);
        u64 v = fma2(acc[q], s, t);
        float a0, a1; unpack2(v, a0, a1);
        y[2 * q] = gelu1(a0); y[2 * q + 1] = gelu1(a1);
    }

    __syncthreads();
#pragma unroll
    for (int c = 0; c < 16; c++) x1s[p * CSTR + ch0 + c] = y[c];
    __syncthreads();

    // ---- conv2 (bn2 folded): thread computes outs [ch0, ch0+16) ----
    u64 acc2[8];
#pragma unroll
    for (int q = 0; q < 8; q++) acc2[q] = *(const u64*)(t2v + ch0 + 2 * q);
    const float4* yb = (const float4*)(x1s + p * CSTR);
#pragma unroll 4
    for (int c4 = 0; c4 < 16; c4++) {
        float4 yv = yb[c4];
        float ya[4] = { yv.x, yv.y, yv.z, yv.w };
#pragma unroll
        for (int cc = 0; cc < 4; cc++) {
            int c = c4 * 4 + cc;
            u64 yp2 = pack2(ya[cc], ya[cc]);
            const ulonglong2* wp = (const ulonglong2*)(w2t + c * 64 + ch0);
#pragma unroll
            for (int q = 0; q < 4; q++) {
                ulonglong2 w = wp[q];
                acc2[2 * q]     = fma2(w.x, yp2, acc2[2 * q]);
                acc2[2 * q + 1] = fma2(w.y, yp2, acc2[2 * q + 1]);
            }
        }
    }

    // ---- mapping skip from x (raw sum; bn folded at the end) ----
    float sk[16];
#pragma unroll
    for (int o = 0; o < 16; o++) sk[o] = 0.f;
    const float* xb2 = x + ((size_t)b << 19) + pix;
#pragma unroll
    for (int hh = 0; hh < 2; hh++) {
        float xh[16];
#pragma unroll
        for (int ci = 0; ci < 16; ci++)
            xh[ci] = __ldg(xb2 + ((size_t)(hh * 16 + ci) << 14));
#pragma unroll
        for (int o = 0; o < 16; o++) {
            const float4* wrow = (const float4*)(wm + (ch0 + o) * 32 + hh * 16);
            float s = 0.f;
#pragma unroll
            for (int c4 = 0; c4 < 4; c4++) {
                float4 w = __ldg(wrow + c4);          // warp-uniform -> L1 broadcast
                s += w.x * xh[c4 * 4] + w.y * xh[c4 * 4 + 1]
                   + w.z * xh[c4 * 4 + 2] + w.w * xh[c4 * 4 + 3];
            }
            sk[o] += s;
        }
    }

    // ---- + folded-bn skip, GELU, store ----
    float* ob = out + ((size_t)b << 20) + pix;
#pragma unroll
    for (int q = 0; q < 8; q++) {
        float a0, a1; unpack2(acc2[q], a0, a1);
        int o0 = ch0 + 2 * q, o1 = o0 + 1;
        float sm0 = __ldg(gm + o0) * rsqrtf(__ldg(vm + o0) + EPS);
        float sm1 = __ldg(gm + o1) * rsqrtf(__ldg(vm + o1) + EPS);
        float tm0 = fmaf(sm0, __ldg(bmap + o0), __ldg(betam + o0)) - __ldg(mm + o0) * sm0;
        float tm1 = fmaf(sm1, __ldg(bmap + o1), __ldg(betam + o1)) - __ldg(mm + o1) * sm1;
        a0 += fmaf(sm0, sk[2 * q],     tm0);
        a1 += fmaf(sm1, sk[2 * q + 1], tm1);
        ob[(size_t)o0 << 14] = gelu1(a0);
        ob[(size_t)o1 << 14] = gelu1(a1);
    }
}

// ===========================================================================
// Launch. Input order: x w1 wr gr br mr vr ws bs g1 b1 m1 v1
//                      w2 g2 b2 m2 v2 wm bmap gm betam mm vm
// ===========================================================================
extern "C" void kernel_launch(void* const* d_in, const int* in_sizes, int n_in,
                              void* d_out, int out_size)
{
    (void)in_sizes; (void)n_in; (void)out_size;
    const float* x     = (const float*)d_in[0];
    const float* w1    = (const float*)d_in[1];
    const float* wr    = (const float*)d_in[2];
    const float* gr    = (const float*)d_in[3];
    const float* br    = (const float*)d_in[4];
    const float* mr    = (const float*)d_in[5];
    const float* vr    = (const float*)d_in[6];
    const float* ws    = (const float*)d_in[7];
    const float* bs    = (const float*)d_in[8];
    const float* g1    = (const float*)d_in[9];
    const float* b1    = (const float*)d_in[10];
    const float* m1    = (const float*)d_in[11];
    const float* v1    = (const float*)d_in[12];
    const float* w2    = (const float*)d_in[13];
    const float* g2    = (const float*)d_in[14];
    const float* b2    = (const float*)d_in[15];
    const float* m2    = (const float*)d_in[16];
    const float* v2    = (const float*)d_in[17];
    const float* wm    = (const float*)d_in[18];
    const float* bmap  = (const float*)d_in[19];
    const float* gm    = (const float*)d_in[20];
    const float* betam = (const float*)d_in[21];
    const float* mm    = (const float*)d_in[22];
    const float* vm    = (const float*)d_in[23];
    float* out = (float*)d_out;

    cudaFuncSetAttribute(k_pre,  cudaFuncAttributeMaxDynamicSharedMemorySize, KP_BYTES);
    cudaFuncSetAttribute(k_main, cudaFuncAttributeMaxDynamicSharedMemorySize, KM_BYTES);

    k_pre<<<512, 256, KP_BYTES>>>(x, w1, wr, gr, br, mr, vr);
    k_main<<<dim3(128 / TW, 128 / TH, 4), 512, KM_BYTES>>>(
        x, wm, bmap, gm, betam, mm, vm,
        ws, bs, g1, b1, m1, v1, w2, g2, b2, m2, v2, out);
}